// round 10
// baseline (speedup 1.0000x reference)
#include <cuda_runtime.h>
#include <cuda_fp16.h>
#include <cstdint>

#define MARGIN   0.3f
#define NEG_FILL 1e9f
#define MAXB 8192
#define MAXE (4096 * 256)

#define TM 128
#define KC 64
#define KST 72                     // row stride elems (144B)
#define TILE_BYTES (128 * 144)     // 18432
#define STAGE_BYTES (2 * TILE_BYTES)

// ---- device scratch (allocation-free rule) ----
__device__ __align__(16) __half g_h[MAXE];
__device__ float g_sq[MAXB];
__device__ int   g_hp[MAXB];
__device__ int   g_hn[MAXB];
__device__ unsigned int g_done;

// ================= prep: fp32->fp16 + norms + init, one warp per row =================
__global__ void prep_kernel(const float* __restrict__ E, int B, int D) {
    const int t = threadIdx.x;
    const int lane = t & 31;
    const int row = blockIdx.x * 8 + (t >> 5);
    const float4* src = (const float4*)(E + (size_t)row * D);
    uint2* ph = (uint2*)(g_h + (size_t)row * D);

    float s = 0.0f;
    #pragma unroll
    for (int q = 0; q < 2; q++) {
        int c = lane + q * 32;
        float4 x = src[c];
        __half2 h0 = __floats2half2_rn(x.x, x.y);
        __half2 h1 = __floats2half2_rn(x.z, x.w);
        uint2 hu;
        hu.x = *(unsigned*)&h0; hu.y = *(unsigned*)&h1;
        ph[c] = hu;
        s = fmaf(x.x, x.x, fmaf(x.y, x.y, fmaf(x.z, x.z, fmaf(x.w, x.w, s))));
    }
    #pragma unroll
    for (int o = 16; o > 0; o >>= 1) s += __shfl_xor_sync(0xffffffffu, s, o);
    if (lane == 0) {
        g_sq[row] = s;
        g_hp[row] = __float_as_int(-1.0f);
        g_hn[row] = __float_as_int(NEG_FILL);
    }
    if (blockIdx.x == 0 && t == 0) g_done = 0u;
}

// ================= mma.sync helpers =================
__device__ __forceinline__ void cp16(uint32_t s, const void* g) {
    asm volatile("cp.async.cg.shared.global [%0], [%1], 16;\n" :: "r"(s), "l"(g));
}
__device__ __forceinline__ void ldsm4(unsigned r[4], const __half* p) {
    unsigned a = (unsigned)__cvta_generic_to_shared(p);
    asm volatile("ldmatrix.sync.aligned.m8n8.x4.shared.b16 {%0,%1,%2,%3}, [%4];"
                 : "=r"(r[0]), "=r"(r[1]), "=r"(r[2]), "=r"(r[3]) : "r"(a));
}
__device__ __forceinline__ void mma_fp16(float c[4], const unsigned a[4], const unsigned* b) {
    asm volatile(
        "mma.sync.aligned.m16n8k16.row.col.f32.f16.f16.f32 "
        "{%0,%1,%2,%3}, {%4,%5,%6,%7}, {%8,%9}, {%0,%1,%2,%3};\n"
        : "+f"(c[0]), "+f"(c[1]), "+f"(c[2]), "+f"(c[3])
        : "r"(a[0]), "r"(a[1]), "r"(a[2]), "r"(a[3]), "r"(b[0]), "r"(b[1]));
}

// ================= main: 128x128 symmetric tiles, fp16 MMA, occ-3 =================
extern __shared__ __half dynsmem[];

__global__ void __launch_bounds__(256, 3)
triplet_mma_sym(const int* __restrict__ L, float* __restrict__ out,
                int B, int D, int nt, int nblk)
{
    const int tid = threadIdx.x;
    const int lane = tid & 31;
    const int w = tid >> 5;
    const int wr = w >> 2, wc = w & 3;       // 2x4 warp grid, 64x32 warp tiles
    const int gid = lane >> 2, tig = lane & 3;
    const int q8 = lane >> 3, r8 = lane & 7;

    // decode upper-triangular (bi <= bj) tile pair
    int u = blockIdx.x;
    float ntf = (float)nt + 0.5f;
    int bi = (int)(ntf - sqrtf(fmaxf(ntf * ntf - 2.0f * (float)u, 0.0f)));
    while (bi > 0 && (bi * nt - bi * (bi - 1) / 2) > u) bi--;
    while (((bi + 1) * nt - (bi + 1) * bi / 2) <= u) bi++;
    int bj = bi + (u - (bi * nt - bi * (bi - 1) / 2));
    const int i0 = bi * TM, j0 = bj * TM;

    __shared__ int s_hpi[TM], s_hni[TM], s_hpj[TM], s_hnj[TM];
    __shared__ bool s_last;
    if (tid < TM) {
        s_hpi[tid] = __float_as_int(-1.0f); s_hni[tid] = __float_as_int(NEG_FILL);
        s_hpj[tid] = __float_as_int(-1.0f); s_hnj[tid] = __float_as_int(NEG_FILL);
    }

    float c[4][4][4];
    #pragma unroll
    for (int mf = 0; mf < 4; mf++)
        #pragma unroll
        for (int nf = 0; nf < 4; nf++)
            #pragma unroll
            for (int r = 0; r < 4; r++) c[mf][nf][r] = 0.0f;

    const uint32_t dsm_a = (uint32_t)__cvta_generic_to_shared(dynsmem);

    // fill one stage: tiles {A, B}, 128 rows x 64 fp16 (128B data, 144B stride)
    auto issue = [&](int kc, int st) {
        const uint32_t sb = dsm_a + st * STAGE_BYTES;
        const int ch = tid & 7;            // 16B chunk in 128B row
        const int r0 = tid >> 3;           // 0..31
        #pragma unroll
        for (int q = 0; q < 8; q++) {
            const int tile = q >> 2;       // 0..1 (A, B)
            const int r = (q & 3) * 32 + r0;
            const int rowg = (tile == 0) ? (i0 + r) : (j0 + r);
            const void* gsrc = g_h + (size_t)rowg * D + kc * KC + ch * 8;
            uint32_t dst = sb + tile * TILE_BYTES + (uint32_t)(r * 144 + ch * 16);
            cp16(dst, gsrc);
        }
        asm volatile("cp.async.commit_group;");
    };

    issue(0, 0);

    const int NKC = D / KC;   // 4
    for (int kc = 0; kc < NKC; kc++) {
        const int cur = kc & 1;
        if (kc + 1 < NKC) {
            issue(kc + 1, cur ^ 1);
            asm volatile("cp.async.wait_group 1;");
        } else {
            asm volatile("cp.async.wait_group 0;");
        }
        __syncthreads();

        const __half* sA = dynsmem + (cur * STAGE_BYTES) / 2;
        const __half* sB = sA + TILE_BYTES / 2;

        #pragma unroll
        for (int ks = 0; ks < KC / 16; ks++) {
            // B fragments: 2 ldsm4, each covers 2 nf groups
            unsigned bf[4][2];
            #pragma unroll
            for (int h = 0; h < 2; h++) {
                int brow = wc * 32 + (2 * h + (q8 >> 1)) * 8 + r8;
                int bcol = ks * 16 + (q8 & 1) * 8;
                unsigned rb[4];
                ldsm4(rb, &sB[brow * KST + bcol]);
                bf[2 * h][0] = rb[0]; bf[2 * h][1] = rb[1];
                bf[2 * h + 1][0] = rb[2]; bf[2 * h + 1][1] = rb[3];
            }
            #pragma unroll
            for (int mf = 0; mf < 4; mf++) {
                int arow = wr * 64 + mf * 16 + (q8 & 1) * 8 + r8;
                int acol = ks * 16 + (q8 >> 1) * 8;
                unsigned af[4];
                ldsm4(af, &sA[arow * KST + acol]);
                #pragma unroll
                for (int nf = 0; nf < 4; nf++)
                    mma_fp16(c[mf][nf], af, bf[nf]);
            }
        }
        __syncthreads();
    }

    // ---- fused epilogue, both anchor sides (scalars re-loaded to save regs) ----
    float hpi[4][2], hni[4][2], hpj[4][2], hnj[4][2];
    #pragma unroll
    for (int x = 0; x < 4; x++)
        #pragma unroll
        for (int y = 0; y < 2; y++) {
            hpi[x][y] = -1.0f; hni[x][y] = NEG_FILL;
            hpj[x][y] = -1.0f; hnj[x][y] = NEG_FILL;
        }

    #pragma unroll
    for (int mf = 0; mf < 4; mf++)
        #pragma unroll
        for (int ro = 0; ro < 2; ro++) {
            const int ig = i0 + wr * 64 + mf * 16 + gid + ro * 8;
            const float si = __ldg(&g_sq[ig]);
            const int   li = __ldg(&L[ig]);
            #pragma unroll
            for (int nf = 0; nf < 4; nf++)
                #pragma unroll
                for (int co = 0; co < 2; co++) {
                    const int jg = j0 + wc * 32 + nf * 8 + tig * 2 + co;
                    float dot = c[mf][nf][ro * 2 + co];
                    float d2 = si + __ldg(&g_sq[jg]) - 2.0f * dot;
                    float d = sqrtf(fmaxf(d2, 0.0f));
                    bool same = (li == __ldg(&L[jg]));
                    bool diag = (ig == jg);
                    if (same) {
                        if (!diag) {
                            hpi[mf][ro] = fmaxf(hpi[mf][ro], d);
                            hpj[nf][co] = fmaxf(hpj[nf][co], d);
                        }
                    } else {
                        hni[mf][ro] = fminf(hni[mf][ro], d);
                        hnj[nf][co] = fminf(hnj[nf][co], d);
                    }
                }
        }

    // i-side: reduce across tig lanes
    #pragma unroll
    for (int mf = 0; mf < 4; mf++)
        #pragma unroll
        for (int ro = 0; ro < 2; ro++) {
            #pragma unroll
            for (int o = 1; o <= 2; o <<= 1) {
                hpi[mf][ro] = fmaxf(hpi[mf][ro], __shfl_xor_sync(0xffffffffu, hpi[mf][ro], o));
                hni[mf][ro] = fminf(hni[mf][ro], __shfl_xor_sync(0xffffffffu, hni[mf][ro], o));
            }
        }
    if (tig == 0) {
        #pragma unroll
        for (int mf = 0; mf < 4; mf++)
            #pragma unroll
            for (int ro = 0; ro < 2; ro++) {
                int rl = wr * 64 + mf * 16 + gid + ro * 8;
                atomicMax(&s_hpi[rl], __float_as_int(hpi[mf][ro]));
                atomicMin(&s_hni[rl], __float_as_int(hni[mf][ro]));
            }
    }

    // j-side: reduce across gid lanes
    #pragma unroll
    for (int nf = 0; nf < 4; nf++)
        #pragma unroll
        for (int co = 0; co < 2; co++) {
            #pragma unroll
            for (int o = 4; o <= 16; o <<= 1) {
                hpj[nf][co] = fmaxf(hpj[nf][co], __shfl_xor_sync(0xffffffffu, hpj[nf][co], o));
                hnj[nf][co] = fminf(hnj[nf][co], __shfl_xor_sync(0xffffffffu, hnj[nf][co], o));
            }
        }
    if (gid == 0) {
        #pragma unroll
        for (int nf = 0; nf < 4; nf++)
            #pragma unroll
            for (int co = 0; co < 2; co++) {
                int cl = wc * 32 + nf * 8 + tig * 2 + co;
                atomicMax(&s_hpj[cl], __float_as_int(hpj[nf][co]));
                atomicMin(&s_hnj[cl], __float_as_int(hnj[nf][co]));
            }
    }
    __syncthreads();

    if (tid < TM) {
        atomicMax(&g_hp[i0 + tid], s_hpi[tid]);
        atomicMin(&g_hn[i0 + tid], s_hni[tid]);
        atomicMax(&g_hp[j0 + tid], s_hpj[tid]);
        atomicMin(&g_hn[j0 + tid], s_hnj[tid]);
    }

    // ---- last-CTA finalize ----
    __threadfence();
    if (tid == 0) s_last = (atomicAdd(&g_done, 1u) == (unsigned)(nblk - 1));
    __syncthreads();
    if (!s_last) return;

    {
        __shared__ float st[8], sc[8];
        float per = 0.0f, cnt = 0.0f;
        for (int i = tid; i < B; i += 256) {
            float hp = __int_as_float(__ldcg(&g_hp[i]));
            float hn = __int_as_float(__ldcg(&g_hn[i]));
            if (hp >= 0.0f && hn < NEG_FILL) {
                per += fmaxf(hp - hn + MARGIN, 0.0f);
                cnt += 1.0f;
            }
        }
        #pragma unroll
        for (int o = 16; o > 0; o >>= 1) {
            per += __shfl_xor_sync(0xffffffffu, per, o);
            cnt += __shfl_xor_sync(0xffffffffu, cnt, o);
        }
        if (lane == 0) { st[w] = per; sc[w] = cnt; }
        __syncthreads();
        if (tid == 0) {
            float tp = 0.0f, tc = 0.0f;
            #pragma unroll
            for (int i = 0; i < 8; i++) { tp += st[i]; tc += sc[i]; }
            out[0] = (tc > 0.0f) ? (tp / fmaxf(tc, 1.0f)) : 0.0f;
        }
    }
}

extern "C" void kernel_launch(void* const* d_in, const int* in_sizes, int n_in,
                              void* d_out, int out_size)
{
    const float* E = (const float*)d_in[0];
    const int* L = (const int*)d_in[1];
    const int B = in_sizes[1];
    const int D = in_sizes[0] / B;
    float* out = (float*)d_out;

    prep_kernel<<<B / 8, 256>>>(E, B, D);

    int nt = B / TM;                       // 32
    int nblk = nt * (nt + 1) / 2;          // 528
    int smembytes = 2 * STAGE_BYTES;       // 73728 per CTA (x3 CTAs = 216KB/SM)
    cudaFuncSetAttribute(triplet_mma_sym,
                         cudaFuncAttributeMaxDynamicSharedMemorySize, smembytes);
    triplet_mma_sym<<<nblk, 256, smembytes>>>(L, out, B, D, nt, nblk);
}

// round 11
// speedup vs baseline: 1.5779x; 1.5779x over previous
#include <cuda_runtime.h>
#include <cuda_fp16.h>
#include <cstdint>

#define MARGIN   0.3f
#define NEG_FILL 1e9f
#define MAXB 8192
#define MAXE (4096 * 256)

#define TM 128
#define KC 64
#define KST 72                     // row stride elems (144B)
#define TILE_BYTES (128 * 144)     // 18432
#define STAGE_BYTES (2 * TILE_BYTES)

// ---- device scratch (allocation-free rule) ----
__device__ __align__(16) __half g_h[MAXE];
__device__ float g_sq[MAXB];
__device__ int   g_hp[MAXB];
__device__ int   g_hn[MAXB];
__device__ unsigned int g_done;

// ================= prep: fp32->fp16 + norms + init, one warp per row =================
__global__ void prep_kernel(const float* __restrict__ E, int B, int D) {
    const int t = threadIdx.x;
    const int lane = t & 31;
    const int row = blockIdx.x * 8 + (t >> 5);
    const float4* src = (const float4*)(E + (size_t)row * D);
    uint2* ph = (uint2*)(g_h + (size_t)row * D);

    float s = 0.0f;
    #pragma unroll
    for (int q = 0; q < 2; q++) {
        int c = lane + q * 32;
        float4 x = src[c];
        __half2 h0 = __floats2half2_rn(x.x, x.y);
        __half2 h1 = __floats2half2_rn(x.z, x.w);
        uint2 hu;
        hu.x = *(unsigned*)&h0; hu.y = *(unsigned*)&h1;
        ph[c] = hu;
        s = fmaf(x.x, x.x, fmaf(x.y, x.y, fmaf(x.z, x.z, fmaf(x.w, x.w, s))));
    }
    #pragma unroll
    for (int o = 16; o > 0; o >>= 1) s += __shfl_xor_sync(0xffffffffu, s, o);
    if (lane == 0) {
        g_sq[row] = s;
        g_hp[row] = __float_as_int(-1.0f);
        g_hn[row] = __float_as_int(NEG_FILL);
    }
    if (blockIdx.x == 0 && t == 0) g_done = 0u;
}

// ================= mma.sync helpers =================
__device__ __forceinline__ void cp16(uint32_t s, const void* g) {
    asm volatile("cp.async.cg.shared.global [%0], [%1], 16;\n" :: "r"(s), "l"(g));
}
__device__ __forceinline__ void ldsm4(unsigned r[4], const __half* p) {
    unsigned a = (unsigned)__cvta_generic_to_shared(p);
    asm volatile("ldmatrix.sync.aligned.m8n8.x4.shared.b16 {%0,%1,%2,%3}, [%4];"
                 : "=r"(r[0]), "=r"(r[1]), "=r"(r[2]), "=r"(r[3]) : "r"(a));
}
__device__ __forceinline__ void mma_fp16(float c[4], const unsigned a[4], const unsigned* b) {
    asm volatile(
        "mma.sync.aligned.m16n8k16.row.col.f32.f16.f16.f32 "
        "{%0,%1,%2,%3}, {%4,%5,%6,%7}, {%8,%9}, {%0,%1,%2,%3};\n"
        : "+f"(c[0]), "+f"(c[1]), "+f"(c[2]), "+f"(c[3])
        : "r"(a[0]), "r"(a[1]), "r"(a[2]), "r"(a[3]), "r"(b[0]), "r"(b[1]));
}

__device__ __forceinline__ void decode_tile(int u, int nt, int& bi, int& bj) {
    float ntf = (float)nt + 0.5f;
    int b = (int)(ntf - sqrtf(fmaxf(ntf * ntf - 2.0f * (float)u, 0.0f)));
    while (b > 0 && (b * nt - b * (b - 1) / 2) > u) b--;
    while (((b + 1) * nt - (b + 1) * b / 2) <= u) b++;
    bi = b;
    bj = b + (u - (b * nt - b * (b - 1) / 2));
}

// ================= main: persistent, 128x128 symmetric tiles, fp16 MMA, occ-2 =================
extern __shared__ __half dynsmem[];

__global__ void __launch_bounds__(256, 2)
triplet_mma_sym(const int* __restrict__ L, float* __restrict__ out,
                int B, int D, int nt, int nblk)
{
    const int tid = threadIdx.x;
    const int lane = tid & 31;
    const int w = tid >> 5;
    const int wr = w >> 2, wc = w & 3;       // 2x4 warp grid, 64x32 warp tiles
    const int gid = lane >> 2, tig = lane & 3;
    const int q8 = lane >> 3, r8 = lane & 7;

    __shared__ int s_hpi[TM], s_hni[TM], s_hpj[TM], s_hnj[TM];
    __shared__ bool s_last;

    const uint32_t dsm_a = (uint32_t)__cvta_generic_to_shared(dynsmem);
    const int NKC = D / KC;   // 4

    // fill one stage's chunk for tile pair (ti0, tj0)
    auto issue = [&](int ti0, int tj0, int kc, int st) {
        const uint32_t sb = dsm_a + st * STAGE_BYTES;
        const int ch = tid & 7;            // 16B chunk in 128B row
        const int r0 = tid >> 3;           // 0..31
        #pragma unroll
        for (int q = 0; q < 8; q++) {
            const int tile = q >> 2;       // 0..1 (A, B)
            const int r = (q & 3) * 32 + r0;
            const int rowg = (tile == 0) ? (ti0 + r) : (tj0 + r);
            const void* gsrc = g_h + (size_t)rowg * D + kc * KC + ch * 8;
            uint32_t dst = sb + tile * TILE_BYTES + (uint32_t)(r * 144 + ch * 16);
            cp16(dst, gsrc);
        }
        asm volatile("cp.async.commit_group;");
    };

    int u = blockIdx.x;
    int bi, bj;
    decode_tile(u, nt, bi, bj);
    int i0 = bi * TM, j0 = bj * TM;
    int stage = 0;
    issue(i0, j0, 0, 0);

    for (; u < nblk; u += gridDim.x) {
        const int un = u + gridDim.x;
        const bool has_next = (un < nblk);
        int i0n = 0, j0n = 0;
        if (has_next) {
            int bin, bjn;
            decode_tile(un, nt, bin, bjn);
            i0n = bin * TM; j0n = bjn * TM;
        }

        float c[4][4][4];
        #pragma unroll
        for (int mf = 0; mf < 4; mf++)
            #pragma unroll
            for (int nf = 0; nf < 4; nf++)
                #pragma unroll
                for (int r = 0; r < 4; r++) c[mf][nf][r] = 0.0f;

        for (int kc = 0; kc < NKC; kc++) {
            const int cur = stage;
            if (kc + 1 < NKC) {
                issue(i0, j0, kc + 1, cur ^ 1);
                asm volatile("cp.async.wait_group 1;");
            } else if (has_next) {
                issue(i0n, j0n, 0, cur ^ 1);     // cross-tile prefetch
                asm volatile("cp.async.wait_group 1;");
            } else {
                asm volatile("cp.async.wait_group 0;");
            }
            __syncthreads();

            const __half* sA = dynsmem + (cur * STAGE_BYTES) / 2;
            const __half* sB = sA + TILE_BYTES / 2;

            #pragma unroll
            for (int ks = 0; ks < KC / 16; ks++) {
                unsigned bf[4][2];
                #pragma unroll
                for (int h = 0; h < 2; h++) {
                    int brow = wc * 32 + (2 * h + (q8 >> 1)) * 8 + r8;
                    int bcol = ks * 16 + (q8 & 1) * 8;
                    unsigned rb[4];
                    ldsm4(rb, &sB[brow * KST + bcol]);
                    bf[2 * h][0] = rb[0]; bf[2 * h][1] = rb[1];
                    bf[2 * h + 1][0] = rb[2]; bf[2 * h + 1][1] = rb[3];
                }
                #pragma unroll
                for (int mf = 0; mf < 4; mf++) {
                    int arow = wr * 64 + mf * 16 + (q8 & 1) * 8 + r8;
                    int acol = ks * 16 + (q8 >> 1) * 8;
                    unsigned af[4];
                    ldsm4(af, &sA[arow * KST + acol]);
                    #pragma unroll
                    for (int nf = 0; nf < 4; nf++)
                        mma_fp16(c[mf][nf], af, bf[nf]);
                }
            }
            __syncthreads();
            stage = cur ^ 1;
        }

        // ---- epilogue (overlaps with next tile's pending chunk-0 load) ----
        if (tid < TM) {
            s_hpi[tid] = __float_as_int(-1.0f); s_hni[tid] = __float_as_int(NEG_FILL);
            s_hpj[tid] = __float_as_int(-1.0f); s_hnj[tid] = __float_as_int(NEG_FILL);
        }
        __syncthreads();

        float hpi[4][2], hni[4][2], hpj[4][2], hnj[4][2];
        #pragma unroll
        for (int x = 0; x < 4; x++)
            #pragma unroll
            for (int y = 0; y < 2; y++) {
                hpi[x][y] = -1.0f; hni[x][y] = NEG_FILL;
                hpj[x][y] = -1.0f; hnj[x][y] = NEG_FILL;
            }

        #pragma unroll
        for (int mf = 0; mf < 4; mf++)
            #pragma unroll
            for (int ro = 0; ro < 2; ro++) {
                const int ig = i0 + wr * 64 + mf * 16 + gid + ro * 8;
                const float si = __ldg(&g_sq[ig]);
                const int   li = __ldg(&L[ig]);
                #pragma unroll
                for (int nf = 0; nf < 4; nf++)
                    #pragma unroll
                    for (int co = 0; co < 2; co++) {
                        const int jg = j0 + wc * 32 + nf * 8 + tig * 2 + co;
                        float dot = c[mf][nf][ro * 2 + co];
                        float d2 = si + __ldg(&g_sq[jg]) - 2.0f * dot;
                        float d = sqrtf(fmaxf(d2, 0.0f));
                        bool same = (li == __ldg(&L[jg]));
                        bool diag = (ig == jg);
                        if (same) {
                            if (!diag) {
                                hpi[mf][ro] = fmaxf(hpi[mf][ro], d);
                                hpj[nf][co] = fmaxf(hpj[nf][co], d);
                            }
                        } else {
                            hni[mf][ro] = fminf(hni[mf][ro], d);
                            hnj[nf][co] = fminf(hnj[nf][co], d);
                        }
                    }
            }

        // i-side: reduce across tig lanes
        #pragma unroll
        for (int mf = 0; mf < 4; mf++)
            #pragma unroll
            for (int ro = 0; ro < 2; ro++) {
                #pragma unroll
                for (int o = 1; o <= 2; o <<= 1) {
                    hpi[mf][ro] = fmaxf(hpi[mf][ro], __shfl_xor_sync(0xffffffffu, hpi[mf][ro], o));
                    hni[mf][ro] = fminf(hni[mf][ro], __shfl_xor_sync(0xffffffffu, hni[mf][ro], o));
                }
            }
        if (tig == 0) {
            #pragma unroll
            for (int mf = 0; mf < 4; mf++)
                #pragma unroll
                for (int ro = 0; ro < 2; ro++) {
                    int rl = wr * 64 + mf * 16 + gid + ro * 8;
                    atomicMax(&s_hpi[rl], __float_as_int(hpi[mf][ro]));
                    atomicMin(&s_hni[rl], __float_as_int(hni[mf][ro]));
                }
        }

        // j-side: reduce across gid lanes
        #pragma unroll
        for (int nf = 0; nf < 4; nf++)
            #pragma unroll
            for (int co = 0; co < 2; co++) {
                #pragma unroll
                for (int o = 4; o <= 16; o <<= 1) {
                    hpj[nf][co] = fmaxf(hpj[nf][co], __shfl_xor_sync(0xffffffffu, hpj[nf][co], o));
                    hnj[nf][co] = fminf(hnj[nf][co], __shfl_xor_sync(0xffffffffu, hnj[nf][co], o));
                }
            }
        if (gid == 0) {
            #pragma unroll
            for (int nf = 0; nf < 4; nf++)
                #pragma unroll
                for (int co = 0; co < 2; co++) {
                    int cl = wc * 32 + nf * 8 + tig * 2 + co;
                    atomicMax(&s_hpj[cl], __float_as_int(hpj[nf][co]));
                    atomicMin(&s_hnj[cl], __float_as_int(hnj[nf][co]));
                }
        }
        __syncthreads();

        if (tid < TM) {
            atomicMax(&g_hp[i0 + tid], s_hpi[tid]);
            atomicMin(&g_hn[i0 + tid], s_hni[tid]);
            atomicMax(&g_hp[j0 + tid], s_hpj[tid]);
            atomicMin(&g_hn[j0 + tid], s_hnj[tid]);
        }
        __syncthreads();

        i0 = i0n; j0 = j0n;
    }

    // ---- last-CTA finalize ----
    __threadfence();
    if (tid == 0) s_last = (atomicAdd(&g_done, 1u) == (unsigned)(gridDim.x - 1));
    __syncthreads();
    if (!s_last) return;

    {
        __shared__ float st[8], sc[8];
        float per = 0.0f, cnt = 0.0f;
        for (int i = tid; i < B; i += 256) {
            float hp = __int_as_float(__ldcg(&g_hp[i]));
            float hn = __int_as_float(__ldcg(&g_hn[i]));
            if (hp >= 0.0f && hn < NEG_FILL) {
                per += fmaxf(hp - hn + MARGIN, 0.0f);
                cnt += 1.0f;
            }
        }
        #pragma unroll
        for (int o = 16; o > 0; o >>= 1) {
            per += __shfl_xor_sync(0xffffffffu, per, o);
            cnt += __shfl_xor_sync(0xffffffffu, cnt, o);
        }
        if (lane == 0) { st[w] = per; sc[w] = cnt; }
        __syncthreads();
        if (tid == 0) {
            float tp = 0.0f, tc = 0.0f;
            #pragma unroll
            for (int i = 0; i < 8; i++) { tp += st[i]; tc += sc[i]; }
            out[0] = (tc > 0.0f) ? (tp / fmaxf(tc, 1.0f)) : 0.0f;
        }
    }
}

extern "C" void kernel_launch(void* const* d_in, const int* in_sizes, int n_in,
                              void* d_out, int out_size)
{
    const float* E = (const float*)d_in[0];
    const int* L = (const int*)d_in[1];
    const int B = in_sizes[1];
    const int D = in_sizes[0] / B;
    float* out = (float*)d_out;

    prep_kernel<<<B / 8, 256>>>(E, B, D);

    int nt = B / TM;                       // 32
    int nblk = nt * (nt + 1) / 2;          // 528
    int grid = 296;                        // 2 CTAs/SM x 148 SMs, persistent
    if (grid > nblk) grid = nblk;
    int smembytes = 2 * STAGE_BYTES;       // 73728 per CTA (x2 CTAs = 144KB/SM)
    cudaFuncSetAttribute(triplet_mma_sym,
                         cudaFuncAttributeMaxDynamicSharedMemorySize, smembytes);
    triplet_mma_sym<<<grid, 256, smembytes>>>(L, out, B, D, nt, nblk);
}

// round 12
// speedup vs baseline: 1.7625x; 1.1170x over previous
#include <cuda_runtime.h>
#include <cuda_fp16.h>
#include <cstdint>

#define MARGIN   0.3f
#define NEG_FILL 1e9f
#define MAXB 8192
#define MAXE (4096 * 256)

#define TM 128
#define KC 64
#define KST 72                     // row stride elems (144B)
#define TILE_BYTES (128 * 144)     // 18432
#define STAGE_BYTES (2 * TILE_BYTES)
#define NSTAGE 3

// ---- device scratch (allocation-free rule) ----
__device__ __align__(16) __half g_h[MAXE];
__device__ float g_sq[MAXB];
__device__ int   g_hp[MAXB];   // squared-distance domain
__device__ int   g_hn[MAXB];   // squared-distance domain
__device__ unsigned int g_done;

// ================= prep: fp32->fp16 + norms + init, one warp per row =================
__global__ void prep_kernel(const float* __restrict__ E, int B, int D) {
    const int t = threadIdx.x;
    const int lane = t & 31;
    const int row = blockIdx.x * 8 + (t >> 5);
    const float4* src = (const float4*)(E + (size_t)row * D);
    uint2* ph = (uint2*)(g_h + (size_t)row * D);

    float s = 0.0f;
    #pragma unroll
    for (int q = 0; q < 2; q++) {
        int c = lane + q * 32;
        float4 x = src[c];
        __half2 h0 = __floats2half2_rn(x.x, x.y);
        __half2 h1 = __floats2half2_rn(x.z, x.w);
        uint2 hu;
        hu.x = *(unsigned*)&h0; hu.y = *(unsigned*)&h1;
        ph[c] = hu;
        s = fmaf(x.x, x.x, fmaf(x.y, x.y, fmaf(x.z, x.z, fmaf(x.w, x.w, s))));
    }
    #pragma unroll
    for (int o = 16; o > 0; o >>= 1) s += __shfl_xor_sync(0xffffffffu, s, o);
    if (lane == 0) {
        g_sq[row] = s;
        g_hp[row] = __float_as_int(-1.0f);
        g_hn[row] = __float_as_int(NEG_FILL);
    }
    if (blockIdx.x == 0 && t == 0) g_done = 0u;
}

// ================= mma.sync helpers =================
__device__ __forceinline__ void cp16(uint32_t s, const void* g) {
    asm volatile("cp.async.cg.shared.global [%0], [%1], 16;\n" :: "r"(s), "l"(g));
}
__device__ __forceinline__ void ldsm4(unsigned r[4], const __half* p) {
    unsigned a = (unsigned)__cvta_generic_to_shared(p);
    asm volatile("ldmatrix.sync.aligned.m8n8.x4.shared.b16 {%0,%1,%2,%3}, [%4];"
                 : "=r"(r[0]), "=r"(r[1]), "=r"(r[2]), "=r"(r[3]) : "r"(a));
}
__device__ __forceinline__ void mma_fp16(float c[4], const unsigned a[4], const unsigned* b) {
    asm volatile(
        "mma.sync.aligned.m16n8k16.row.col.f32.f16.f16.f32 "
        "{%0,%1,%2,%3}, {%4,%5,%6,%7}, {%8,%9}, {%0,%1,%2,%3};\n"
        : "+f"(c[0]), "+f"(c[1]), "+f"(c[2]), "+f"(c[3])
        : "r"(a[0]), "r"(a[1]), "r"(a[2]), "r"(a[3]), "r"(b[0]), "r"(b[1]));
}

// ================= main: 128x128 symmetric tiles, fp16 MMA, occ-2, 3-stage =================
extern __shared__ __half dynsmem[];

__global__ void __launch_bounds__(256, 2)
triplet_mma_sym(const int* __restrict__ L, float* __restrict__ out,
                int B, int D, int nt, int nblk)
{
    const int tid = threadIdx.x;
    const int lane = tid & 31;
    const int w = tid >> 5;
    const int wr = w >> 2, wc = w & 3;       // 2x4 warp grid, 64x32 warp tiles
    const int gid = lane >> 2, tig = lane & 3;
    const int q8 = lane >> 3, r8 = lane & 7;

    // decode upper-triangular (bi <= bj) tile pair
    int u = blockIdx.x;
    float ntf = (float)nt + 0.5f;
    int bi = (int)(ntf - sqrtf(fmaxf(ntf * ntf - 2.0f * (float)u, 0.0f)));
    while (bi > 0 && (bi * nt - bi * (bi - 1) / 2) > u) bi--;
    while (((bi + 1) * nt - (bi + 1) * bi / 2) <= u) bi++;
    int bj = bi + (u - (bi * nt - bi * (bi - 1) / 2));
    const int i0 = bi * TM, j0 = bj * TM;

    __shared__ int s_hpi[TM], s_hni[TM], s_hpj[TM], s_hnj[TM];
    __shared__ bool s_last;
    if (tid < TM) {
        s_hpi[tid] = __float_as_int(-1.0f); s_hni[tid] = __float_as_int(NEG_FILL);
        s_hpj[tid] = __float_as_int(-1.0f); s_hnj[tid] = __float_as_int(NEG_FILL);
    }

    float c[4][4][4];
    #pragma unroll
    for (int mf = 0; mf < 4; mf++)
        #pragma unroll
        for (int nf = 0; nf < 4; nf++)
            #pragma unroll
            for (int r = 0; r < 4; r++) c[mf][nf][r] = 0.0f;

    const uint32_t dsm_a = (uint32_t)__cvta_generic_to_shared(dynsmem);

    // fill one stage: tiles {A, B}, 128 rows x 64 fp16 (128B data, 144B stride)
    auto issue = [&](int kc, int st) {
        const uint32_t sb = dsm_a + st * STAGE_BYTES;
        const int ch = tid & 7;            // 16B chunk in 128B row
        const int r0 = tid >> 3;           // 0..31
        #pragma unroll
        for (int q = 0; q < 8; q++) {
            const int tile = q >> 2;       // 0..1 (A, B)
            const int r = (q & 3) * 32 + r0;
            const int rowg = (tile == 0) ? (i0 + r) : (j0 + r);
            const void* gsrc = g_h + (size_t)rowg * D + kc * KC + ch * 8;
            uint32_t dst = sb + tile * TILE_BYTES + (uint32_t)(r * 144 + ch * 16);
            cp16(dst, gsrc);
        }
        asm volatile("cp.async.commit_group;");
    };

    const int NKC = D / KC;   // 4
    issue(0, 0);
    issue(1, 1);

    for (int kc = 0; kc < NKC; kc++) {
        const int cur = kc % NSTAGE;
        if (kc + 2 < NKC) {
            issue(kc + 2, (kc + 2) % NSTAGE);
            asm volatile("cp.async.wait_group 2;");
        } else if (kc + 1 < NKC) {
            asm volatile("cp.async.wait_group 1;");
        } else {
            asm volatile("cp.async.wait_group 0;");
        }
        __syncthreads();

        const __half* sA = dynsmem + (cur * STAGE_BYTES) / 2;
        const __half* sB = sA + TILE_BYTES / 2;

        #pragma unroll
        for (int ks = 0; ks < KC / 16; ks++) {
            // B fragments: 2 ldsm4, each covers 2 nf groups
            unsigned bf[4][2];
            #pragma unroll
            for (int h = 0; h < 2; h++) {
                int brow = wc * 32 + (2 * h + (q8 >> 1)) * 8 + r8;
                int bcol = ks * 16 + (q8 & 1) * 8;
                unsigned rb[4];
                ldsm4(rb, &sB[brow * KST + bcol]);
                bf[2 * h][0] = rb[0]; bf[2 * h][1] = rb[1];
                bf[2 * h + 1][0] = rb[2]; bf[2 * h + 1][1] = rb[3];
            }
            #pragma unroll
            for (int mf = 0; mf < 4; mf++) {
                int arow = wr * 64 + mf * 16 + (q8 & 1) * 8 + r8;
                int acol = ks * 16 + (q8 >> 1) * 8;
                unsigned af[4];
                ldsm4(af, &sA[arow * KST + acol]);
                #pragma unroll
                for (int nf = 0; nf < 4; nf++)
                    mma_fp16(c[mf][nf], af, bf[nf]);
            }
        }
        __syncthreads();
    }

    // ---- fused epilogue in SQUARED-distance space (sqrt deferred to finalize) ----
    float hpi[4][2], hni[4][2], hpj[4][2], hnj[4][2];
    #pragma unroll
    for (int x = 0; x < 4; x++)
        #pragma unroll
        for (int y = 0; y < 2; y++) {
            hpi[x][y] = -1.0f; hni[x][y] = NEG_FILL;
            hpj[x][y] = -1.0f; hnj[x][y] = NEG_FILL;
        }

    #pragma unroll
    for (int mf = 0; mf < 4; mf++)
        #pragma unroll
        for (int ro = 0; ro < 2; ro++) {
            const int ig = i0 + wr * 64 + mf * 16 + gid + ro * 8;
            const float si = __ldg(&g_sq[ig]);
            const int   li = __ldg(&L[ig]);
            #pragma unroll
            for (int nf = 0; nf < 4; nf++)
                #pragma unroll
                for (int co = 0; co < 2; co++) {
                    const int jg = j0 + wc * 32 + nf * 8 + tig * 2 + co;
                    float dot = c[mf][nf][ro * 2 + co];
                    float d2 = fmaxf(si + __ldg(&g_sq[jg]) - 2.0f * dot, 0.0f);
                    bool same = (li == __ldg(&L[jg]));
                    bool diag = (ig == jg);
                    if (same) {
                        if (!diag) {
                            hpi[mf][ro] = fmaxf(hpi[mf][ro], d2);
                            hpj[nf][co] = fmaxf(hpj[nf][co], d2);
                        }
                    } else {
                        hni[mf][ro] = fminf(hni[mf][ro], d2);
                        hnj[nf][co] = fminf(hnj[nf][co], d2);
                    }
                }
        }

    // i-side: reduce across tig lanes
    #pragma unroll
    for (int mf = 0; mf < 4; mf++)
        #pragma unroll
        for (int ro = 0; ro < 2; ro++) {
            #pragma unroll
            for (int o = 1; o <= 2; o <<= 1) {
                hpi[mf][ro] = fmaxf(hpi[mf][ro], __shfl_xor_sync(0xffffffffu, hpi[mf][ro], o));
                hni[mf][ro] = fminf(hni[mf][ro], __shfl_xor_sync(0xffffffffu, hni[mf][ro], o));
            }
        }
    if (tig == 0) {
        #pragma unroll
        for (int mf = 0; mf < 4; mf++)
            #pragma unroll
            for (int ro = 0; ro < 2; ro++) {
                int rl = wr * 64 + mf * 16 + gid + ro * 8;
                atomicMax(&s_hpi[rl], __float_as_int(hpi[mf][ro]));
                atomicMin(&s_hni[rl], __float_as_int(hni[mf][ro]));
            }
    }

    // j-side: reduce across gid lanes
    #pragma unroll
    for (int nf = 0; nf < 4; nf++)
        #pragma unroll
        for (int co = 0; co < 2; co++) {
            #pragma unroll
            for (int o = 4; o <= 16; o <<= 1) {
                hpj[nf][co] = fmaxf(hpj[nf][co], __shfl_xor_sync(0xffffffffu, hpj[nf][co], o));
                hnj[nf][co] = fminf(hnj[nf][co], __shfl_xor_sync(0xffffffffu, hnj[nf][co], o));
            }
        }
    if (gid == 0) {
        #pragma unroll
        for (int nf = 0; nf < 4; nf++)
            #pragma unroll
            for (int co = 0; co < 2; co++) {
                int cl = wc * 32 + nf * 8 + tig * 2 + co;
                atomicMax(&s_hpj[cl], __float_as_int(hpj[nf][co]));
                atomicMin(&s_hnj[cl], __float_as_int(hnj[nf][co]));
            }
    }
    __syncthreads();

    if (tid < TM) {
        atomicMax(&g_hp[i0 + tid], s_hpi[tid]);
        atomicMin(&g_hn[i0 + tid], s_hni[tid]);
        atomicMax(&g_hp[j0 + tid], s_hpj[tid]);
        atomicMin(&g_hn[j0 + tid], s_hnj[tid]);
    }

    // ---- last-CTA finalize (sqrt applied here) ----
    __threadfence();
    if (tid == 0) s_last = (atomicAdd(&g_done, 1u) == (unsigned)(nblk - 1));
    __syncthreads();
    if (!s_last) return;

    {
        __shared__ float st[8], sc[8];
        float per = 0.0f, cnt = 0.0f;
        for (int i = tid; i < B; i += 256) {
            float hp2 = __int_as_float(__ldcg(&g_hp[i]));
            float hn2 = __int_as_float(__ldcg(&g_hn[i]));
            if (hp2 >= 0.0f && hn2 < NEG_FILL) {
                per += fmaxf(sqrtf(hp2) - sqrtf(hn2) + MARGIN, 0.0f);
                cnt += 1.0f;
            }
        }
        #pragma unroll
        for (int o = 16; o > 0; o >>= 1) {
            per += __shfl_xor_sync(0xffffffffu, per, o);
            cnt += __shfl_xor_sync(0xffffffffu, cnt, o);
        }
        if (lane == 0) { st[w] = per; sc[w] = cnt; }
        __syncthreads();
        if (tid == 0) {
            float tp = 0.0f, tc = 0.0f;
            #pragma unroll
            for (int i = 0; i < 8; i++) { tp += st[i]; tc += sc[i]; }
            out[0] = (tc > 0.0f) ? (tp / fmaxf(tc, 1.0f)) : 0.0f;
        }
    }
}

extern "C" void kernel_launch(void* const* d_in, const int* in_sizes, int n_in,
                              void* d_out, int out_size)
{
    const float* E = (const float*)d_in[0];
    const int* L = (const int*)d_in[1];
    const int B = in_sizes[1];
    const int D = in_sizes[0] / B;
    float* out = (float*)d_out;

    prep_kernel<<<B / 8, 256>>>(E, B, D);

    int nt = B / TM;                       // 32
    int nblk = nt * (nt + 1) / 2;          // 528
    int smembytes = NSTAGE * STAGE_BYTES;  // 110592 per CTA (x2 CTAs = 221KB/SM)
    cudaFuncSetAttribute(triplet_mma_sym,
                         cudaFuncAttributeMaxDynamicSharedMemorySize, smembytes);
    triplet_mma_sym<<<nblk, 256, smembytes>>>(L, out, B, D, nt, nblk);
}

// round 14
// speedup vs baseline: 1.8567x; 1.0535x over previous
#include <cuda_runtime.h>
#include <cuda_fp16.h>
#include <cstdint>

#define MARGIN   0.3f
#define NEG_FILL 1e9f
#define MAXB 8192
#define MAXE (4096 * 256)

#define TM 128
#define KC 64
#define KST 72                     // row stride elems (144B)
#define TILE_BYTES (128 * 144)     // 18432
// smem: A chunks 0..3 at [0, 4*TILE), B stages at [4*TILE, 6*TILE)
#define SMEM_TOTAL (6 * TILE_BYTES)   // 110592

// ---- device scratch (allocation-free rule) ----
__device__ __align__(16) __half g_h[MAXE];
__device__ float g_sq[MAXB];
__device__ int   g_hp[MAXB];   // squared-distance domain
__device__ int   g_hn[MAXB];   // squared-distance domain
__device__ unsigned int g_done;

// ================= prep: fp32->fp16 + norms + init, one warp per row =================
__global__ void prep_kernel(const float* __restrict__ E, int B, int D) {
    const int t = threadIdx.x;
    const int lane = t & 31;
    const int row = blockIdx.x * 8 + (t >> 5);
    const float4* src = (const float4*)(E + (size_t)row * D);
    uint2* ph = (uint2*)(g_h + (size_t)row * D);

    float s = 0.0f;
    #pragma unroll
    for (int q = 0; q < 2; q++) {
        int c = lane + q * 32;
        float4 x = src[c];
        __half2 h0 = __floats2half2_rn(x.x, x.y);
        __half2 h1 = __floats2half2_rn(x.z, x.w);
        uint2 hu;
        hu.x = *(unsigned*)&h0; hu.y = *(unsigned*)&h1;
        ph[c] = hu;
        s = fmaf(x.x, x.x, fmaf(x.y, x.y, fmaf(x.z, x.z, fmaf(x.w, x.w, s))));
    }
    #pragma unroll
    for (int o = 16; o > 0; o >>= 1) s += __shfl_xor_sync(0xffffffffu, s, o);
    if (lane == 0) {
        g_sq[row] = s;
        g_hp[row] = __float_as_int(-1.0f);
        g_hn[row] = __float_as_int(NEG_FILL);
    }
    if (blockIdx.x == 0 && t == 0) g_done = 0u;
}

// ================= mma.sync helpers =================
__device__ __forceinline__ void cp16(uint32_t s, const void* g) {
    asm volatile("cp.async.cg.shared.global [%0], [%1], 16;\n" :: "r"(s), "l"(g));
}
__device__ __forceinline__ void ldsm4(unsigned r[4], const __half* p) {
    unsigned a = (unsigned)__cvta_generic_to_shared(p);
    asm volatile("ldmatrix.sync.aligned.m8n8.x4.shared.b16 {%0,%1,%2,%3}, [%4];"
                 : "=r"(r[0]), "=r"(r[1]), "=r"(r[2]), "=r"(r[3]) : "r"(a));
}
__device__ __forceinline__ void mma_fp16(float c[4], const unsigned a[4], const unsigned* b) {
    asm volatile(
        "mma.sync.aligned.m16n8k16.row.col.f32.f16.f16.f32 "
        "{%0,%1,%2,%3}, {%4,%5,%6,%7}, {%8,%9}, {%0,%1,%2,%3};\n"
        : "+f"(c[0]), "+f"(c[1]), "+f"(c[2]), "+f"(c[3])
        : "r"(a[0]), "r"(a[1]), "r"(a[2]), "r"(a[3]), "r"(b[0]), "r"(b[1]));
}

// ================= main: A-resident 128x256 super-tiles, fp16 MMA, occ-2 =================
extern __shared__ __half dynsmem[];

__global__ void __launch_bounds__(256, 2)
triplet_mma_sym(const int* __restrict__ L, float* __restrict__ out,
                int B, int D, int nsj, int nblk)
{
    const int tid = threadIdx.x;
    const int lane = tid & 31;
    const int w = tid >> 5;
    const int wr = w >> 2, wc = w & 3;       // 2x4 warp grid, 64x32 warp tiles
    const int gid = lane >> 2, tig = lane & 3;
    const int q8 = lane >> 3, r8 = lane & 7;

    // decode (bi, bjs): bjs >= bi/2, row bi has (nsj - bi/2) entries
    int rem = blockIdx.x;
    int bi = 0;
    while (rem >= (nsj - (bi >> 1))) { rem -= (nsj - (bi >> 1)); bi++; }
    const int bjs = (bi >> 1) + rem;
    const int i0 = bi * TM;

    __shared__ int s_hpi[TM], s_hni[TM], s_hpj[TM], s_hnj[TM];
    __shared__ bool s_last;
    if (tid < TM) {
        s_hpi[tid] = __float_as_int(-1.0f); s_hni[tid] = __float_as_int(NEG_FILL);
        s_hpj[tid] = __float_as_int(-1.0f); s_hnj[tid] = __float_as_int(NEG_FILL);
    }

    const uint32_t dsm_a = (uint32_t)__cvta_generic_to_shared(dynsmem);

    // A: 4 chunk-tiles, loaded once (one commit group)
    {
        const int ch = tid & 7, r0 = tid >> 3;
        #pragma unroll
        for (int k = 0; k < 4; k++) {
            #pragma unroll
            for (int q = 0; q < 4; q++) {
                const int r = q * 32 + r0;
                const void* gsrc = g_h + (size_t)(i0 + r) * D + k * KC + ch * 8;
                uint32_t dst = dsm_a + k * TILE_BYTES + (uint32_t)(r * 144 + ch * 16);
                cp16(dst, gsrc);
            }
        }
        asm volatile("cp.async.commit_group;");
    }

    // B chunk loader: phase p, chunk kcl, stage st
    auto issueB = [&](int j0, int kcl, int st) {
        const int ch = tid & 7, r0 = tid >> 3;
        #pragma unroll
        for (int q = 0; q < 4; q++) {
            const int r = q * 32 + r0;
            const void* gsrc = g_h + (size_t)(j0 + r) * D + kcl * KC + ch * 8;
            uint32_t dst = dsm_a + (4 + st) * TILE_BYTES + (uint32_t)(r * 144 + ch * 16);
            cp16(dst, gsrc);
        }
        asm volatile("cp.async.commit_group;");
    };

    const int j0p[2] = { (2 * bjs) * TM, (2 * bjs + 1) * TM };

    // hpi accumulators persist across both phases (d^2 domain)
    float hpi[4][2], hni[4][2];
    #pragma unroll
    for (int x = 0; x < 4; x++)
        #pragma unroll
        for (int y = 0; y < 2; y++) { hpi[x][y] = -1.0f; hni[x][y] = NEG_FILL; }

    float c[4][4][4];
    #pragma unroll
    for (int mf = 0; mf < 4; mf++)
        #pragma unroll
        for (int nf = 0; nf < 4; nf++)
            #pragma unroll
            for (int r = 0; r < 4; r++) c[mf][nf][r] = 0.0f;

    issueB(j0p[0], 0, 0);

    for (int cc = 0; cc < 8; cc++) {
        const int kcl = cc & 3;
        if (cc + 1 < 8) {
            issueB(j0p[(cc + 1) >> 2], (cc + 1) & 3, (cc + 1) & 1);
            asm volatile("cp.async.wait_group 1;");
        } else {
            asm volatile("cp.async.wait_group 0;");
        }
        __syncthreads();

        const __half* sA = dynsmem + (kcl * TILE_BYTES) / 2;
        const __half* sB = dynsmem + ((4 + (cc & 1)) * TILE_BYTES) / 2;

        #pragma unroll
        for (int ks = 0; ks < KC / 16; ks++) {
            unsigned bf[4][2];
            #pragma unroll
            for (int h = 0; h < 2; h++) {
                int brow = wc * 32 + (2 * h + (q8 >> 1)) * 8 + r8;
                int bcol = ks * 16 + (q8 & 1) * 8;
                unsigned rb[4];
                ldsm4(rb, &sB[brow * KST + bcol]);
                bf[2 * h][0] = rb[0]; bf[2 * h][1] = rb[1];
                bf[2 * h + 1][0] = rb[2]; bf[2 * h + 1][1] = rb[3];
            }
            #pragma unroll
            for (int mf = 0; mf < 4; mf++) {
                int arow = wr * 64 + mf * 16 + (q8 & 1) * 8 + r8;
                int acol = ks * 16 + (q8 >> 1) * 8;
                unsigned af[4];
                ldsm4(af, &sA[arow * KST + acol]);
                #pragma unroll
                for (int nf = 0; nf < 4; nf++)
                    mma_fp16(c[mf][nf], af, bf[nf]);
            }
        }
        __syncthreads();

        // ---- phase boundary: fold accumulators (overlaps next phase's B load) ----
        if (kcl == 3) {
            const int p = cc >> 2;
            const int j0 = j0p[p];

            float hpj[4][2], hnj[4][2];
            #pragma unroll
            for (int x = 0; x < 4; x++)
                #pragma unroll
                for (int y = 0; y < 2; y++) { hpj[x][y] = -1.0f; hnj[x][y] = NEG_FILL; }

            #pragma unroll
            for (int mf = 0; mf < 4; mf++)
                #pragma unroll
                for (int ro = 0; ro < 2; ro++) {
                    const int ig = i0 + wr * 64 + mf * 16 + gid + ro * 8;
                    const float si = __ldg(&g_sq[ig]);
                    const int   li = __ldg(&L[ig]);
                    #pragma unroll
                    for (int nf = 0; nf < 4; nf++)
                        #pragma unroll
                        for (int co = 0; co < 2; co++) {
                            const int jg = j0 + wc * 32 + nf * 8 + tig * 2 + co;
                            float dot = c[mf][nf][ro * 2 + co];
                            float d2 = fmaxf(si + __ldg(&g_sq[jg]) - 2.0f * dot, 0.0f);
                            bool same = (li == __ldg(&L[jg]));
                            bool diag = (ig == jg);
                            if (same) {
                                if (!diag) {
                                    hpi[mf][ro] = fmaxf(hpi[mf][ro], d2);
                                    hpj[nf][co] = fmaxf(hpj[nf][co], d2);
                                }
                            } else {
                                hni[mf][ro] = fminf(hni[mf][ro], d2);
                                hnj[nf][co] = fminf(hnj[nf][co], d2);
                            }
                        }
                }

            // j-side: reduce across gid lanes, then shared+global atomics
            #pragma unroll
            for (int nf = 0; nf < 4; nf++)
                #pragma unroll
                for (int co = 0; co < 2; co++) {
                    #pragma unroll
                    for (int o = 4; o <= 16; o <<= 1) {
                        hpj[nf][co] = fmaxf(hpj[nf][co], __shfl_xor_sync(0xffffffffu, hpj[nf][co], o));
                        hnj[nf][co] = fminf(hnj[nf][co], __shfl_xor_sync(0xffffffffu, hnj[nf][co], o));
                    }
                }
            if (gid == 0) {
                #pragma unroll
                for (int nf = 0; nf < 4; nf++)
                    #pragma unroll
                    for (int co = 0; co < 2; co++) {
                        int cl = wc * 32 + nf * 8 + tig * 2 + co;
                        atomicMax(&s_hpj[cl], __float_as_int(hpj[nf][co]));
                        atomicMin(&s_hnj[cl], __float_as_int(hnj[nf][co]));
                    }
            }
            __syncthreads();
            if (tid < TM) {
                atomicMax(&g_hp[j0 + tid], s_hpj[tid]);
                atomicMin(&g_hn[j0 + tid], s_hnj[tid]);
                s_hpj[tid] = __float_as_int(-1.0f);     // reinit for phase 1
                s_hnj[tid] = __float_as_int(NEG_FILL);
            }
            __syncthreads();

            // reset accumulators for next phase
            #pragma unroll
            for (int mf = 0; mf < 4; mf++)
                #pragma unroll
                for (int nf = 0; nf < 4; nf++)
                    #pragma unroll
                    for (int r = 0; r < 4; r++) c[mf][nf][r] = 0.0f;
        }
    }

    // ---- i-side fold (once per CTA) ----
    #pragma unroll
    for (int mf = 0; mf < 4; mf++)
        #pragma unroll
        for (int ro = 0; ro < 2; ro++) {
            #pragma unroll
            for (int o = 1; o <= 2; o <<= 1) {
                hpi[mf][ro] = fmaxf(hpi[mf][ro], __shfl_xor_sync(0xffffffffu, hpi[mf][ro], o));
                hni[mf][ro] = fminf(hni[mf][ro], __shfl_xor_sync(0xffffffffu, hni[mf][ro], o));
            }
        }
    if (tig == 0) {
        #pragma unroll
        for (int mf = 0; mf < 4; mf++)
            #pragma unroll
            for (int ro = 0; ro < 2; ro++) {
                int rl = wr * 64 + mf * 16 + gid + ro * 8;
                atomicMax(&s_hpi[rl], __float_as_int(hpi[mf][ro]));
                atomicMin(&s_hni[rl], __float_as_int(hni[mf][ro]));
            }
    }
    __syncthreads();
    if (tid < TM) {
        atomicMax(&g_hp[i0 + tid], s_hpi[tid]);
        atomicMin(&g_hn[i0 + tid], s_hni[tid]);
    }

    // ---- last-CTA finalize (sqrt applied here) ----
    __threadfence();
    if (tid == 0) s_last = (atomicAdd(&g_done, 1u) == (unsigned)(nblk - 1));
    __syncthreads();
    if (!s_last) return;

    {
        __shared__ float st[8], sc[8];
        float per = 0.0f, cnt = 0.0f;
        for (int i = tid; i < B; i += 256) {
            float hp2 = __int_as_float(__ldcg(&g_hp[i]));
            float hn2 = __int_as_float(__ldcg(&g_hn[i]));
            if (hp2 >= 0.0f && hn2 < NEG_FILL) {
                per += fmaxf(sqrtf(hp2) - sqrtf(hn2) + MARGIN, 0.0f);
                cnt += 1.0f;
            }
        }
        #pragma unroll
        for (int o = 16; o > 0; o >>= 1) {
            per += __shfl_xor_sync(0xffffffffu, per, o);
            cnt += __shfl_xor_sync(0xffffffffu, cnt, o);
        }
        if (lane == 0) { st[w] = per; sc[w] = cnt; }
        __syncthreads();
        if (tid == 0) {
            float tp = 0.0f, tc = 0.0f;
            #pragma unroll
            for (int i = 0; i < 8; i++) { tp += st[i]; tc += sc[i]; }
            out[0] = (tc > 0.0f) ? (tp / fmaxf(tc, 1.0f)) : 0.0f;
        }
    }
}

extern "C" void kernel_launch(void* const* d_in, const int* in_sizes, int n_in,
                              void* d_out, int out_size)
{
    const float* E = (const float*)d_in[0];
    const int* L = (const int*)d_in[1];
    const int B = in_sizes[1];
    const int D = in_sizes[0] / B;
    float* out = (float*)d_out;

    prep_kernel<<<B / 8, 256>>>(E, B, D);

    int nti = B / TM;                   // 32
    int nsj = B / (2 * TM);             // 16
    // nblk = sum_{bi=0}^{nti-1} (nsj - bi/2)
    int nblk = 0;
    for (int bi = 0; bi < nti; bi++) nblk += nsj - (bi >> 1);   // 272

    cudaFuncSetAttribute(triplet_mma_sym,
                         cudaFuncAttributeMaxDynamicSharedMemorySize, SMEM_TOTAL);
    triplet_mma_sym<<<nblk, 256, SMEM_TOTAL>>>(L, out, B, D, nsj, nblk);
}